// round 6
// baseline (speedup 1.0000x reference)
#include <cuda_runtime.h>
#include <cuda_bf16.h>

#define NNODES 1024
#define FIN    256
#define DIN    128
#define DOUT   64
#define MAX_DEG 120   // mean deg ~64, std ~7.7; 120 is ~7 sigma, P(overflow) ~ 1e-10
#define BT      32    // sib tile width (b-dimension)

// Scratch (device globals; no allocation allowed in kernel_launch)
__device__ int   g_nbr[NNODES * MAX_DEG];
__device__ int   g_deg[NNODES];
__device__ float g_wc[FIN * DOUT];      // lin_w^T @ weight  (256 x 64)
__device__ float g_bias2[DOUT];         // lin_b @ weight
__device__ float g_wf[NNODES * DOUT];   // node embeddings after both linears

// ---------------------------------------------------------------------------
// Build per-node neighbor lists from adjacency rows (deterministic, no atomics)
// One block per row, 1024 threads, ballot + warp-count prefix scan.
// ---------------------------------------------------------------------------
__global__ void build_nbrs_kernel(const float* __restrict__ A) {
    int row  = blockIdx.x;
    int t    = threadIdx.x;                 // column index
    bool pred = A[row * NNODES + t] != 0.0f;
    unsigned mask = __ballot_sync(0xffffffffu, pred);
    int lane = t & 31, w = t >> 5;

    __shared__ int wcount[32];
    __shared__ int wbase[32];
    if (lane == 0) wcount[w] = __popc(mask);
    __syncthreads();
    if (t == 0) {
        int s = 0;
        #pragma unroll
        for (int i = 0; i < 32; i++) { wbase[i] = s; s += wcount[i]; }
        g_deg[row] = (s < MAX_DEG) ? s : MAX_DEG;
    }
    __syncthreads();
    if (pred) {
        int pos = wbase[w] + __popc(mask & ((1u << lane) - 1u));
        if (pos < MAX_DEG) g_nbr[row * MAX_DEG + pos] = t;
    }
}

// ---------------------------------------------------------------------------
// Wc[f][o] = sum_d lin_w[d][f] * weight[d][o]   (256x64, 2M FMA)
// ---------------------------------------------------------------------------
__global__ void wc_kernel(const float* __restrict__ lin_w,
                          const float* __restrict__ weight) {
    int gid = blockIdx.x * blockDim.x + threadIdx.x;   // 0 .. 16383
    int f = gid >> 6, o = gid & 63;
    float acc = 0.0f;
    #pragma unroll 4
    for (int d = 0; d < DIN; d++)
        acc = fmaf(lin_w[d * FIN + f], weight[d * DOUT + o], acc);
    g_wc[f * DOUT + o] = acc;
}

__global__ void bias2_kernel(const float* __restrict__ lin_b,
                             const float* __restrict__ weight) {
    int o = threadIdx.x;  // 0..63
    float acc = 0.0f;
    #pragma unroll 4
    for (int d = 0; d < DIN; d++)
        acc = fmaf(lin_b[d], weight[d * DOUT + o], acc);
    g_bias2[o] = acc;
}

// ---------------------------------------------------------------------------
// wf[n][o] = sum_f nf[n][f] * Wc[f][o] + bias2[o]   (1024x64, 17M FMA)
// ---------------------------------------------------------------------------
__global__ void wf_kernel(const float* __restrict__ nf) {
    int gid = blockIdx.x * blockDim.x + threadIdx.x;   // 0 .. 65535
    int n = gid >> 6, o = gid & 63;
    float acc = g_bias2[o];
    const float* __restrict__ nfr = nf + n * FIN;
    #pragma unroll 8
    for (int f = 0; f < FIN; f++)
        acc = fmaf(nfr[f], g_wc[f * DOUT + o], acc);
    g_wf[n * DOUT + o] = acc;
}

// ---------------------------------------------------------------------------
// Main: out[i,f] = (1/nc[i]^2) * sum_{j,b in nbrs(i)} wf[j,f]*sib[j,b]*wf[b,f]
// One block per node i, 256 threads = 64 f-lanes x 4 j-groups.
// Stages: neighbor wf rows (deg x 64) and sib tiles (deg x 32) in shared.
// ---------------------------------------------------------------------------
__global__ __launch_bounds__(256)
void interact_kernel(const float* __restrict__ sib,
                     const float* __restrict__ nc,
                     float* __restrict__ out) {
    __shared__ int   s_nbr[MAX_DEG];
    __shared__ float s_wf[MAX_DEG][DOUT];    // 30 KB
    __shared__ float s_sib[MAX_DEG][BT];     // 15 KB
    __shared__ float s_part[4][DOUT];        // 1 KB

    const int i   = blockIdx.x;
    const int tid = threadIdx.x;
    const int deg = g_deg[i];

    for (int idx = tid; idx < deg; idx += 256)
        s_nbr[idx] = g_nbr[i * MAX_DEG + idx];
    __syncthreads();

    // Gather neighbor embeddings (coalesced 64-float rows)
    for (int idx = tid; idx < deg * DOUT; idx += 256) {
        int j = idx >> 6, f = idx & 63;
        s_wf[j][f] = g_wf[s_nbr[j] * DOUT + f];
    }

    const int f   = tid & 63;
    const int grp = tid >> 6;   // 0..3
    float acc = 0.0f;

    for (int b0 = 0; b0 < deg; b0 += BT) {
        int bt = min(BT, deg - b0);
        __syncthreads();   // protect s_sib from previous tile's readers (also covers s_wf first time)
        // Gather sib tile: sib[nbr[j]][nbr[b0+bb]]
        for (int idx = tid; idx < deg * BT; idx += 256) {
            int j = idx >> 5, bb = idx & 31;
            if (bb < bt)
                s_sib[j][bb] = sib[(size_t)s_nbr[j] * NNODES + s_nbr[b0 + bb]];
        }
        __syncthreads();

        for (int j = grp; j < deg; j += 4) {
            float inner = 0.0f;
            #pragma unroll 8
            for (int bb = 0; bb < bt; bb++)
                inner = fmaf(s_sib[j][bb], s_wf[b0 + bb][f], inner);
            acc = fmaf(s_wf[j][f], inner, acc);
        }
    }

    s_part[grp][f] = acc;
    __syncthreads();
    if (tid < DOUT) {
        float v = s_part[0][tid] + s_part[1][tid] + s_part[2][tid] + s_part[3][tid];
        float c = nc[i];
        out[i * DOUT + tid] = v / (c * c);
    }
}

// ---------------------------------------------------------------------------
// Input order (metadata): 0 node_features, 1 adjacency_matrix, 2 mask_father,
// 3 neighbor_count, 4 mask_hadamard(=sib), 5 lin_w, 6 lin_b, 7 weight
// ---------------------------------------------------------------------------
extern "C" void kernel_launch(void* const* d_in, const int* in_sizes, int n_in,
                              void* d_out, int out_size) {
    const float* nf     = (const float*)d_in[0];
    const float* A      = (const float*)d_in[1];
    const float* ncount = (const float*)d_in[3];
    const float* sib    = (const float*)d_in[4];
    const float* lin_w  = (const float*)d_in[5];
    const float* lin_b  = (const float*)d_in[6];
    const float* weight = (const float*)d_in[7];
    float* out = (float*)d_out;

    build_nbrs_kernel<<<NNODES, 1024>>>(A);
    wc_kernel<<<(FIN * DOUT) / 256, 256>>>(lin_w, weight);
    bias2_kernel<<<1, DOUT>>>(lin_b, weight);
    wf_kernel<<<(NNODES * DOUT) / 256, 256>>>(nf);
    interact_kernel<<<NNODES, 256>>>(sib, ncount, out);
}

// round 10
// speedup vs baseline: 1.8648x; 1.8648x over previous
#include <cuda_runtime.h>
#include <cuda_bf16.h>

#define NNODES 1024
#define FIN    256
#define DIN    128
#define DOUT   64
#define MAX_DEG 120   // mean deg ~64, std ~7.7; 120 ~ 7 sigma
#define BT2    16     // symmetric tile edge

// Scratch (device globals; no allocation allowed)
__device__ int   g_nbr[NNODES * MAX_DEG];
__device__ int   g_deg[NNODES];
__device__ float g_wc[FIN * DOUT];      // lin_w^T @ weight  (256 x 64)
__device__ float g_bias2[DOUT];         // lin_b @ weight
__device__ float g_wf[NNODES * DOUT];   // node embeddings after both linears

// ---------------------------------------------------------------------------
// Per-node neighbor lists (deterministic ballot compaction)
// ---------------------------------------------------------------------------
__global__ void build_nbrs_kernel(const float* __restrict__ A) {
    int row  = blockIdx.x;
    int t    = threadIdx.x;
    bool pred = A[row * NNODES + t] != 0.0f;
    unsigned mask = __ballot_sync(0xffffffffu, pred);
    int lane = t & 31, w = t >> 5;

    __shared__ int wcount[32];
    __shared__ int wbase[32];
    if (lane == 0) wcount[w] = __popc(mask);
    __syncthreads();
    if (t == 0) {
        int s = 0;
        #pragma unroll
        for (int i = 0; i < 32; i++) { wbase[i] = s; s += wcount[i]; }
        g_deg[row] = (s < MAX_DEG) ? s : MAX_DEG;
    }
    __syncthreads();
    if (pred) {
        int pos = wbase[w] + __popc(mask & ((1u << lane) - 1u));
        if (pos < MAX_DEG) g_nbr[row * MAX_DEG + pos] = t;
    }
}

// ---------------------------------------------------------------------------
// Wc[f][o] = sum_d lin_w[d][f]*weight[d][o]; block FIN computes bias2.
// grid = FIN+1 blocks x 64 threads
// ---------------------------------------------------------------------------
__global__ __launch_bounds__(64)
void wc_kernel(const float* __restrict__ lin_w,
               const float* __restrict__ weight,
               const float* __restrict__ lin_b) {
    int o = threadIdx.x;
    if (blockIdx.x == FIN) {            // bias2[o] = sum_d lin_b[d]*weight[d][o]
        float a0 = 0.f, a1 = 0.f;
        #pragma unroll 8
        for (int d = 0; d < DIN; d += 2) {
            a0 = fmaf(lin_b[d],     weight[d * DOUT + o],       a0);
            a1 = fmaf(lin_b[d + 1], weight[(d + 1) * DOUT + o], a1);
        }
        g_bias2[o] = a0 + a1;
        return;
    }
    int f = blockIdx.x;
    float a0 = 0.f, a1 = 0.f, a2 = 0.f, a3 = 0.f;
    #pragma unroll 4
    for (int d = 0; d < DIN; d += 4) {
        a0 = fmaf(lin_w[d * FIN + f],       weight[d * DOUT + o],       a0);
        a1 = fmaf(lin_w[(d + 1) * FIN + f], weight[(d + 1) * DOUT + o], a1);
        a2 = fmaf(lin_w[(d + 2) * FIN + f], weight[(d + 2) * DOUT + o], a2);
        a3 = fmaf(lin_w[(d + 3) * FIN + f], weight[(d + 3) * DOUT + o], a3);
    }
    g_wc[f * DOUT + o] = (a0 + a1) + (a2 + a3);
}

// ---------------------------------------------------------------------------
// wf[n][o] = sum_f nf[n][f]*Wc[f][o] + bias2[o]
// float4 + 4 independent accumulators for MLP (was latency-bound @18.4us)
// ---------------------------------------------------------------------------
__global__ __launch_bounds__(256)
void wf_kernel(const float* __restrict__ nf) {
    int gid = blockIdx.x * 256 + threadIdx.x;
    int n = gid >> 6, o = gid & 63;
    const float4* __restrict__ nf4 = (const float4*)(nf + n * FIN);
    float a0 = 0.f, a1 = 0.f, a2 = 0.f, a3 = 0.f;
    #pragma unroll 8
    for (int q = 0; q < FIN / 4; q++) {
        float4 v = nf4[q];
        const float* __restrict__ wc = g_wc + (q * 4) * DOUT + o;
        a0 = fmaf(v.x, wc[0],        a0);
        a1 = fmaf(v.y, wc[DOUT],     a1);
        a2 = fmaf(v.z, wc[2 * DOUT], a2);
        a3 = fmaf(v.w, wc[3 * DOUT], a3);
    }
    g_wf[gid] = ((a0 + a1) + (a2 + a3)) + g_bias2[o];
}

// ---------------------------------------------------------------------------
// out[i,f] = (1/nc[i]^2) * sum_{j,b in N(i)} wf[j,f]*sib[j,b]*wf[b,f]
//
// Symmetric 16x16 tiling: pairs (J,B<=J), off-diagonal pairs weighted x2
// (folded into register-cached wb; valid because sib = A0@A0 + A0 is
// symmetric). sib tile gather prefetched into a register to overlap
// latency with FMA. One block per node, 256 threads = 64 f-lanes x 4
// j-groups.
// ---------------------------------------------------------------------------
__global__ __launch_bounds__(256)
void interact_kernel(const float* __restrict__ sib,
                     const float* __restrict__ nc,
                     float* __restrict__ out) {
    __shared__ int s_nbr[128];
    __shared__ __align__(16) float s_wf[128][DOUT];   // 32 KB, zero-padded rows
    __shared__ __align__(16) float s_sib[BT2][BT2];   // 1 KB
    __shared__ float s_part[4][DOUT];

    const int i    = blockIdx.x;
    const int tid  = threadIdx.x;
    const int deg  = g_deg[i];
    const int T    = (deg + BT2 - 1) / BT2;
    const int degP = T * BT2;                         // <= 128

    for (int idx = tid; idx < deg; idx += 256)
        s_nbr[idx] = g_nbr[i * MAX_DEG + idx];
    __syncthreads();

    // Stage neighbor embeddings, zero-padded to degP rows (float4 rows)
    for (int idx = tid; idx < degP * 16; idx += 256) {
        int j = idx >> 4, q = idx & 15;
        float4 v = make_float4(0.f, 0.f, 0.f, 0.f);
        if (j < deg) v = ((const float4*)(g_wf + s_nbr[j] * DOUT))[q];
        ((float4*)(&s_wf[j][0]))[q] = v;
    }
    // (fenced by the first __syncthreads inside the pair loop)

    const int f   = tid & 63;
    const int grp = tid >> 6;
    const int jr0 = grp * 4;               // 4 tile-rows per thread group
    const int my_jr = tid >> 4, my_bc = tid & 15;   // gather: 1 elem/thread
    float acc = 0.f;

    const int npairs = T * (T + 1) / 2;
    int J = 0, B = 0;
    float pre;
    {   // prefetch pair 0
        int jg = my_jr, bg = my_bc;   // J=0,B=0
        pre = (jg < deg && bg < deg)
            ? sib[(size_t)s_nbr[jg] * NNODES + s_nbr[bg]] : 0.f;
    }

    for (int p = 0; p < npairs; p++) {
        __syncthreads();                  // prior compute done reading s_sib
        s_sib[my_jr][my_bc] = pre;
        __syncthreads();

        int Jc = J, Bc = B;
        if (++B > J) { B = 0; ++J; }
        if (p + 1 < npairs) {             // prefetch next tile (overlaps compute)
            int jg = J * BT2 + my_jr, bg = B * BT2 + my_bc;
            pre = (jg < deg && bg < deg)
                ? sib[(size_t)s_nbr[jg] * NNODES + s_nbr[bg]] : 0.f;
        }

        float fac = (Bc < Jc) ? 2.f : 1.f;
        float wb[BT2];
        #pragma unroll
        for (int bb = 0; bb < BT2; bb++)
            wb[bb] = fac * s_wf[Bc * BT2 + bb][f];

        #pragma unroll
        for (int jj = 0; jj < 4; jj++) {
            int r = jr0 + jj;                       // row within J tile
            const float4* sr = (const float4*)(&s_sib[r][0]);
            float4 a = sr[0], b4 = sr[1], c4 = sr[2], d4 = sr[3];
            float i0 = a.x * wb[0],  i1 = a.y * wb[1];
            float i2 = a.z * wb[2],  i3 = a.w * wb[3];
            i0 = fmaf(b4.x, wb[4],  i0); i1 = fmaf(b4.y, wb[5],  i1);
            i2 = fmaf(b4.z, wb[6],  i2); i3 = fmaf(b4.w, wb[7],  i3);
            i0 = fmaf(c4.x, wb[8],  i0); i1 = fmaf(c4.y, wb[9],  i1);
            i2 = fmaf(c4.z, wb[10], i2); i3 = fmaf(c4.w, wb[11], i3);
            i0 = fmaf(d4.x, wb[12], i0); i1 = fmaf(d4.y, wb[13], i1);
            i2 = fmaf(d4.z, wb[14], i2); i3 = fmaf(d4.w, wb[15], i3);
            float inner = (i0 + i1) + (i2 + i3);
            acc = fmaf(s_wf[Jc * BT2 + r][f], inner, acc);
        }
    }

    s_part[grp][f] = acc;
    __syncthreads();
    if (tid < DOUT) {
        float v = s_part[0][tid] + s_part[1][tid] + s_part[2][tid] + s_part[3][tid];
        float c = nc[i];
        out[i * DOUT + tid] = v / (c * c);
    }
}

// ---------------------------------------------------------------------------
// Inputs: 0 node_features, 1 adjacency, 2 mask_father, 3 neighbor_count,
//         4 mask_hadamard(=sib), 5 lin_w, 6 lin_b, 7 weight
// ---------------------------------------------------------------------------
extern "C" void kernel_launch(void* const* d_in, const int* in_sizes, int n_in,
                              void* d_out, int out_size) {
    const float* nf     = (const float*)d_in[0];
    const float* A      = (const float*)d_in[1];
    const float* ncount = (const float*)d_in[3];
    const float* sib    = (const float*)d_in[4];
    const float* lin_w  = (const float*)d_in[5];
    const float* lin_b  = (const float*)d_in[6];
    const float* weight = (const float*)d_in[7];
    float* out = (float*)d_out;

    build_nbrs_kernel<<<NNODES, 1024>>>(A);
    wc_kernel<<<FIN + 1, 64>>>(lin_w, weight, lin_b);
    wf_kernel<<<(NNODES * DOUT) / 256, 256>>>(nf);
    interact_kernel<<<NNODES, 256>>>(sib, ncount, out);
}

// round 13
// speedup vs baseline: 2.3532x; 1.2619x over previous
#include <cuda_runtime.h>
#include <cuda_bf16.h>

#define NNODES 1024
#define FIN    256
#define DIN    128
#define DOUT   64
#define BT2    16     // symmetric tile edge
#define MAXP   128    // padded neighbor capacity (deg ~64±7.6; 128 is ~8 sigma)

// Scratch (device globals; no allocation allowed)
__device__ float g_wc[FIN * DOUT];      // lin_w^T @ weight  (256 x 64)
__device__ float g_bias2[DOUT];         // lin_b @ weight
__device__ float g_wf[NNODES * DOUT];   // node embeddings after both linears

// ---------------------------------------------------------------------------
// Wc[f][o] = sum_d lin_w[d][f]*weight[d][o]; block FIN computes bias2.
// ---------------------------------------------------------------------------
__global__ __launch_bounds__(64)
void wc_kernel(const float* __restrict__ lin_w,
               const float* __restrict__ weight,
               const float* __restrict__ lin_b) {
    int o = threadIdx.x;
    if (blockIdx.x == FIN) {
        float a0 = 0.f, a1 = 0.f;
        #pragma unroll 8
        for (int d = 0; d < DIN; d += 2) {
            a0 = fmaf(lin_b[d],     weight[d * DOUT + o],       a0);
            a1 = fmaf(lin_b[d + 1], weight[(d + 1) * DOUT + o], a1);
        }
        g_bias2[o] = a0 + a1;
        return;
    }
    int f = blockIdx.x;
    float a0 = 0.f, a1 = 0.f, a2 = 0.f, a3 = 0.f;
    #pragma unroll 4
    for (int d = 0; d < DIN; d += 4) {
        a0 = fmaf(lin_w[d * FIN + f],       weight[d * DOUT + o],       a0);
        a1 = fmaf(lin_w[(d + 1) * FIN + f], weight[(d + 1) * DOUT + o], a1);
        a2 = fmaf(lin_w[(d + 2) * FIN + f], weight[(d + 2) * DOUT + o], a2);
        a3 = fmaf(lin_w[(d + 3) * FIN + f], weight[(d + 3) * DOUT + o], a3);
    }
    g_wc[f * DOUT + o] = (a0 + a1) + (a2 + a3);
}

// ---------------------------------------------------------------------------
// wf[n][o] = sum_f nf[n][f]*Wc[f][o] + bias2[o]
// ---------------------------------------------------------------------------
__global__ __launch_bounds__(256)
void wf_kernel(const float* __restrict__ nf) {
    int gid = blockIdx.x * 256 + threadIdx.x;
    int n = gid >> 6, o = gid & 63;
    const float4* __restrict__ nf4 = (const float4*)(nf + n * FIN);
    float a0 = 0.f, a1 = 0.f, a2 = 0.f, a3 = 0.f;
    #pragma unroll 8
    for (int q = 0; q < FIN / 4; q++) {
        float4 v = nf4[q];
        const float* __restrict__ wc = g_wc + (q * 4) * DOUT + o;
        a0 = fmaf(v.x, wc[0],        a0);
        a1 = fmaf(v.y, wc[DOUT],     a1);
        a2 = fmaf(v.z, wc[2 * DOUT], a2);
        a3 = fmaf(v.w, wc[3 * DOUT], a3);
    }
    g_wf[gid] = ((a0 + a1) + (a2 + a3)) + g_bias2[o];
}

// ---------------------------------------------------------------------------
// out[i,f] = (1/nc[i]^2) * sum_{j,b in N(i)} wf[j,f]*sib[j,b]*wf[b,f]
//
// v3: inline neighbor-list build (ballot compaction over the block's own
// adjacency row); symmetric column-major pair loop with wb hoisted per
// B-column (diagonal tile at fac=1, then wb *= 2 for off-diagonal tiles);
// double-buffered s_sib -> 1 sync per pair; s_nbr padded with a valid index
// so the gather is branch-free (padded rows of s_wf are zero, annihilating
// any padded contribution).
// ---------------------------------------------------------------------------
__global__ __launch_bounds__(256)
void interact_kernel(const float* __restrict__ A,
                     const float* __restrict__ sib,
                     const float* __restrict__ nc,
                     float* __restrict__ out) {
    __shared__ int      s_nbr[MAXP];
    __shared__ unsigned s_mask[32];
    __shared__ int      s_base[33];
    __shared__ __align__(16) float s_wf[MAXP][DOUT];       // 32 KB
    __shared__ __align__(16) float s_sib[2][BT2][BT2];     // 2 KB
    __shared__ float s_part[4][DOUT];

    const int i    = blockIdx.x;
    const int tid  = threadIdx.x;
    const int w    = tid >> 5, lane = tid & 31;

    // ---- build neighbor list from A row i (4 chunks of 256 cols) ----
    bool pr[4];
    #pragma unroll
    for (int c = 0; c < 4; c++) {
        float a = A[i * NNODES + c * 256 + tid];
        pr[c] = (a != 0.0f);
        unsigned m = __ballot_sync(0xffffffffu, pr[c]);
        if (lane == 0) s_mask[c * 8 + w] = m;
    }
    __syncthreads();
    if (tid == 0) {
        int s = 0;
        #pragma unroll
        for (int k = 0; k < 32; k++) { s_base[k] = s; s += __popc(s_mask[k]); }
        s_base[32] = s;
    }
    __syncthreads();
    const unsigned lmask = (1u << lane) - 1u;
    #pragma unroll
    for (int c = 0; c < 4; c++) {
        if (pr[c]) {
            int pos = s_base[c * 8 + w] + __popc(s_mask[c * 8 + w] & lmask);
            if (pos < MAXP) s_nbr[pos] = c * 256 + tid;
        }
    }
    const int deg  = min(s_base[32], MAXP);   // deg >= 1 (self-loop)
    const int T    = (deg + BT2 - 1) / BT2;
    const int degP = T * BT2;
    __syncthreads();

    // pad s_nbr with a valid node index (gather reads stay in-bounds)
    const int n0 = s_nbr[0];
    if (tid < degP - deg) s_nbr[deg + tid] = n0;

    // stage neighbor embeddings, zero-padded to degP rows
    for (int idx = tid; idx < degP * 16; idx += 256) {
        int j = idx >> 4, q = idx & 15;
        float4 v = make_float4(0.f, 0.f, 0.f, 0.f);
        if (j < deg) v = ((const float4*)(g_wf + s_nbr[j] * DOUT))[q];
        ((float4*)(&s_wf[j][0]))[q] = v;
    }
    __syncthreads();   // s_nbr padding + s_wf staging complete

    const int f     = tid & 63;
    const int grp   = tid >> 6;
    const int jr0   = grp * 4;
    const int my_jr = tid >> 4, my_bc = tid & 15;
    float acc = 0.f;
    int  pb  = 0;

    // prefetch pair (Bc=0, Jc=0)
    float pre = sib[(size_t)s_nbr[my_jr] * NNODES + s_nbr[my_bc]];

    for (int Bc = 0; Bc < T; Bc++) {
        float wb[BT2];
        #pragma unroll
        for (int bb = 0; bb < BT2; bb++)
            wb[bb] = s_wf[Bc * BT2 + bb][f];      // fac=1 for the diagonal tile

        for (int Jc = Bc; Jc < T; Jc++) {
            s_sib[pb][my_jr][my_bc] = pre;
            __syncthreads();

            // prefetch next pair (column-major over the lower triangle)
            int nJ = Jc + 1, nB = Bc;
            if (nJ >= T) { nB = Bc + 1; nJ = nB; }
            if (nB < T)
                pre = sib[(size_t)s_nbr[nJ * BT2 + my_jr] * NNODES
                          + s_nbr[nB * BT2 + my_bc]];

            #pragma unroll
            for (int jj = 0; jj < 4; jj++) {
                int r = jr0 + jj;
                const float4* sr = (const float4*)(&s_sib[pb][r][0]);
                float4 a = sr[0], b4 = sr[1], c4 = sr[2], d4 = sr[3];
                float i0 = a.x * wb[0],  i1 = a.y * wb[1];
                float i2 = a.z * wb[2],  i3 = a.w * wb[3];
                i0 = fmaf(b4.x, wb[4],  i0); i1 = fmaf(b4.y, wb[5],  i1);
                i2 = fmaf(b4.z, wb[6],  i2); i3 = fmaf(b4.w, wb[7],  i3);
                i0 = fmaf(c4.x, wb[8],  i0); i1 = fmaf(c4.y, wb[9],  i1);
                i2 = fmaf(c4.z, wb[10], i2); i3 = fmaf(c4.w, wb[11], i3);
                i0 = fmaf(d4.x, wb[12], i0); i1 = fmaf(d4.y, wb[13], i1);
                i2 = fmaf(d4.z, wb[14], i2); i3 = fmaf(d4.w, wb[15], i3);
                float inner = (i0 + i1) + (i2 + i3);
                acc = fmaf(s_wf[Jc * BT2 + r][f], inner, acc);
            }

            if (Jc == Bc) {            // after the diagonal tile: x2 for symmetry
                #pragma unroll
                for (int bb = 0; bb < BT2; bb++) wb[bb] += wb[bb];
            }
            pb ^= 1;
        }
    }

    s_part[grp][f] = acc;
    __syncthreads();
    if (tid < DOUT) {
        float v = s_part[0][tid] + s_part[1][tid] + s_part[2][tid] + s_part[3][tid];
        float c = nc[i];
        out[i * DOUT + tid] = v / (c * c);
    }
}

// ---------------------------------------------------------------------------
// Inputs: 0 node_features, 1 adjacency, 2 mask_father, 3 neighbor_count,
//         4 mask_hadamard(=sib), 5 lin_w, 6 lin_b, 7 weight
// ---------------------------------------------------------------------------
extern "C" void kernel_launch(void* const* d_in, const int* in_sizes, int n_in,
                              void* d_out, int out_size) {
    const float* nf     = (const float*)d_in[0];
    const float* A      = (const float*)d_in[1];
    const float* ncount = (const float*)d_in[3];
    const float* sib    = (const float*)d_in[4];
    const float* lin_w  = (const float*)d_in[5];
    const float* lin_b  = (const float*)d_in[6];
    const float* weight = (const float*)d_in[7];
    float* out = (float*)d_out;

    wc_kernel<<<FIN + 1, 64>>>(lin_w, weight, lin_b);
    wf_kernel<<<(NNODES * DOUT) / 256, 256>>>(nf);
    interact_kernel<<<NNODES, 256>>>(A, sib, ncount, out);
}